// round 11
// baseline (speedup 1.0000x reference)
#include <cuda_runtime.h>
#include <cuda_bf16.h>
#include <math.h>

// Problem constants (fixed-shape problem)
#define MAXN 50000
#define MAXE 800000
#define FDIM 128
#define CDIM 8
#define MAXB ((MAXN + 255) / 256)   // max scan blocks (196)

#define KTOT 384                    // split-K: [a_hi | a_lo | a_hi] vs [w_hi | w_hi | w_lo]
#define SA   392                    // padded bf16 row stride (392*2B = 784B, 16B-aligned, %32-bank-safe)

// ---------------- scratch (static __device__, no allocation) ----------------
__device__ int   d_is64;
__device__ int   d_cnt[MAXN];
__device__ int   d_offs[MAXN + 1];
__device__ int   d_cursor[MAXN];
__device__ float d_dinv[MAXN];
__device__ int   d_csr[MAXE];
__device__ int   d_bsum[MAXB];
__device__ int   d_boff[MAXB];
__device__ float d_bufA[(size_t)MAXN * FDIM];
__device__ float d_bufB[(size_t)MAXN * FDIM];

// ---------------- edge dtype detection ----------------
__global__ void detect_kernel(const unsigned int* __restrict__ w) {
    if (threadIdx.x == 0 && blockIdx.x == 0) {
        unsigned int acc = 0;
        #pragma unroll
        for (int i = 0; i < 64; i++) acc |= w[2 * i + 1];
        d_is64 = (acc == 0) ? 1 : 0;
    }
}

// ---------------- CSR construction ----------------
__global__ void zero_cnt_kernel(int n) {
    int i = blockIdx.x * blockDim.x + threadIdx.x;
    if (i < n) d_cnt[i] = 0;
}

__global__ void hist_kernel(const int* __restrict__ w, int e) {
    int i = blockIdx.x * blockDim.x + threadIdx.x;
    if (i < e) {
        int c = d_is64 ? w[2 * (e + i)] : w[e + i];
        atomicAdd(&d_cnt[c], 1);
    }
}

__global__ void bsum_kernel(int n) {
    const int b = blockIdx.x;
    const int tid = threadIdx.x;
    int i = b * 256 + tid;
    int v = (i < n) ? d_cnt[i] : 0;
    #pragma unroll
    for (int o = 16; o; o >>= 1) v += __shfl_xor_sync(0xffffffffu, v, o);
    __shared__ int ws[8];
    if ((tid & 31) == 0) ws[tid >> 5] = v;
    __syncthreads();
    if (tid == 0) {
        int s = 0;
        #pragma unroll
        for (int j = 0; j < 8; j++) s += ws[j];
        d_bsum[b] = s;
    }
}

__global__ void bscan_kernel(int nb) {
    const int tid = threadIdx.x, lane = tid & 31, wid = tid >> 5;
    int v = (tid < nb) ? d_bsum[tid] : 0;
    int x = v;
    #pragma unroll
    for (int o = 1; o < 32; o <<= 1) {
        int t = __shfl_up_sync(0xffffffffu, x, o);
        if (lane >= o) x += t;
    }
    __shared__ int ws[32];
    if (lane == 31) ws[wid] = x;
    __syncthreads();
    if (wid == 0) {
        int s = ws[lane];
        #pragma unroll
        for (int o = 1; o < 32; o <<= 1) {
            int t = __shfl_up_sync(0xffffffffu, s, o);
            if (lane >= o) s += t;
        }
        ws[lane] = s;
    }
    __syncthreads();
    int incl = x + (wid ? ws[wid - 1] : 0);
    if (tid < nb) d_boff[tid] = incl - v;
}

__global__ void scan_apply_kernel(int n) {
    const int b = blockIdx.x;
    const int tid = threadIdx.x, lane = tid & 31, wid = tid >> 5;
    int i = b * 256 + tid;
    int v = (i < n) ? d_cnt[i] : 0;
    int x = v;
    #pragma unroll
    for (int o = 1; o < 32; o <<= 1) {
        int t = __shfl_up_sync(0xffffffffu, x, o);
        if (lane >= o) x += t;
    }
    __shared__ int ws[8];
    if (lane == 31) ws[wid] = x;
    __syncthreads();
    if (wid == 0 && lane < 8) {
        int s = ws[lane];
        #pragma unroll
        for (int o = 1; o < 8; o <<= 1) {
            int t = __shfl_up_sync(0x000000ffu, s, o);
            if (lane >= o) s += t;
        }
        ws[lane] = s;
    }
    __syncthreads();
    int incl = x + (wid ? ws[wid - 1] : 0) + d_boff[b];
    if (i < n) {
        d_offs[i + 1] = incl;
        d_cursor[i]   = incl - v;
        d_dinv[i]     = rsqrtf((float)(v + 1));
        if (i == 0) d_offs[0] = 0;
    }
}

__global__ void scatter_kernel(const int* __restrict__ w, int e) {
    int i = blockIdx.x * blockDim.x + threadIdx.x;
    if (i < e) {
        int is64 = d_is64;
        int c = is64 ? w[2 * (e + i)] : w[e + i];
        int r = is64 ? w[2 * i]       : w[i];
        int p = atomicAdd(&d_cursor[c], 1);
        d_csr[p] = r;
    }
}

// ---------------- Tensor-core GEMM (split bf16): out = dinv .* (A @ W) ----------------
// block 256 thr = 8 warps (4 m-warps x 2 n-warps); output tile 64 rows x 128 cols.
// K' = 384: A' = [hi|lo|hi], W' = [hi|hi|lo]; mma.sync m16n8k16 bf16, fp32 accum.
#define LDSM_X4(r0, r1, r2, r3, addr) \
    asm volatile("ldmatrix.sync.aligned.m8n8.x4.shared.b16 {%0,%1,%2,%3}, [%4];" \
                 : "=r"(r0), "=r"(r1), "=r"(r2), "=r"(r3) : "r"(addr))

#define MMA16816(d, a0, a1, a2, a3, b0, b1) \
    asm volatile("mma.sync.aligned.m16n8k16.row.col.f32.bf16.bf16.f32 " \
                 "{%0,%1,%2,%3}, {%4,%5,%6,%7}, {%8,%9}, {%0,%1,%2,%3};" \
                 : "+f"(d[0]), "+f"(d[1]), "+f"(d[2]), "+f"(d[3]) \
                 : "r"(a0), "r"(a1), "r"(a2), "r"(a3), "r"(b0), "r"(b1))

__global__ void __launch_bounds__(256) gemm_tc_kernel(
    const float* __restrict__ A, const float* __restrict__ W,
    float* __restrict__ out, int n)
{
    extern __shared__ __nv_bfloat16 sh[];
    __nv_bfloat16* As = sh;             // [64][SA]
    __nv_bfloat16* Bs = sh + 64 * SA;   // [128][SA]  (Wt: row n, col k)
    const int tid = threadIdx.x;
    const int row0 = blockIdx.x * 64;

    // fill W' (transposed, split)
    for (int e = tid; e < 128 * 128; e += 256) {
        int k = e >> 7, nn = e & 127;
        float w = W[e];                       // W[k][n], row-major
        __nv_bfloat16 hi = __float2bfloat16(w);
        __nv_bfloat16 lo = __float2bfloat16(w - __bfloat162float(hi));
        Bs[nn * SA + k]       = hi;
        Bs[nn * SA + k + 128] = hi;
        Bs[nn * SA + k + 256] = lo;
    }
    // fill A' (split): 64 rows x 32 float4
    #pragma unroll
    for (int i = 0; i < 8; i++) {
        int idx = tid + i * 256;
        int r = idx >> 5, kq = (idx & 31) * 4;
        float4 v = make_float4(0.f, 0.f, 0.f, 0.f);
        int gr = row0 + r;
        if (gr < n) v = ((const float4*)A)[(size_t)gr * 32 + (idx & 31)];
        float f[4] = {v.x, v.y, v.z, v.w};
        #pragma unroll
        for (int c = 0; c < 4; c++) {
            __nv_bfloat16 hi = __float2bfloat16(f[c]);
            __nv_bfloat16 lo = __float2bfloat16(f[c] - __bfloat162float(hi));
            As[r * SA + kq + c]       = hi;
            As[r * SA + 128 + kq + c] = lo;
            As[r * SA + 256 + kq + c] = hi;
        }
    }
    __syncthreads();

    const int wid = tid >> 5, l = tid & 31;
    const int wm = wid & 3, wn = wid >> 2;

    // ldmatrix lane base addresses (byte, shared space)
    // A: row = wm*16 + (l&7) + ((l>>3)&1)*8 ; k-offset = (l>>4)*8
    unsigned aAddr = (unsigned)__cvta_generic_to_shared(
        As + (wm * 16 + (l & 7) + ((l >> 3) & 1) * 8) * SA + (l >> 4) * 8);
    // B: n = wn*64 + t*16 + (l&7) + (l>>4)*8 ; k-offset = ((l>>3)&1)*8
    unsigned bAddr[4];
    #pragma unroll
    for (int t = 0; t < 4; t++)
        bAddr[t] = (unsigned)__cvta_generic_to_shared(
            Bs + (wn * 64 + t * 16 + (l & 7) + (l >> 4) * 8) * SA + ((l >> 3) & 1) * 8);

    float acc[8][4];
    #pragma unroll
    for (int j = 0; j < 8; j++)
        #pragma unroll
        for (int q = 0; q < 4; q++) acc[j][q] = 0.f;

    #pragma unroll 2
    for (int kt = 0; kt < KTOT / 16; kt++) {
        unsigned a0, a1, a2, a3;
        LDSM_X4(a0, a1, a2, a3, aAddr + kt * 32);      // 16 bf16 = 32B per step
        #pragma unroll
        for (int t = 0; t < 4; t++) {
            unsigned b0, b1, b2, b3;
            LDSM_X4(b0, b1, b2, b3, bAddr[t] + kt * 32);
            MMA16816(acc[2 * t],     a0, a1, a2, a3, b0, b1);
            MMA16816(acc[2 * t + 1], a0, a1, a2, a3, b2, b3);
        }
    }

    // epilogue: c frag: row = l/4 (+8), col = 2(l%4)+{0,1}
    const int rl = wm * 16 + (l >> 2);
    const int cb = wn * 64 + 2 * (l & 3);
    int r0g = row0 + rl, r1g = row0 + rl + 8;
    float s0 = (r0g < n) ? d_dinv[r0g] : 0.f;
    float s1 = (r1g < n) ? d_dinv[r1g] : 0.f;
    #pragma unroll
    for (int t = 0; t < 8; t++) {
        int c = cb + t * 8;
        if (r0g < n) {
            float2 v = make_float2(acc[t][0] * s0, acc[t][1] * s0);
            *(float2*)(out + (size_t)r0g * 128 + c) = v;
        }
        if (r1g < n) {
            float2 v = make_float2(acc[t][2] * s1, acc[t][3] * s1);
            *(float2*)(out + (size_t)r1g * 128 + c) = v;
        }
    }
}

// ---------------- Aggregation: warp per node (proven R4/R6 version) ----------------
__global__ void agg_kernel(const float* __restrict__ g, const float* __restrict__ bias,
                           float* __restrict__ outh, int n)
{
    const int warp = (blockIdx.x * blockDim.x + threadIdx.x) >> 5;
    const int lane = threadIdx.x & 31;
    if (warp >= n) return;
    const int node = warp;

    float4 acc = *(const float4*)(g + (size_t)node * 128 + lane * 4);  // self loop
    const int s = d_offs[node], e = d_offs[node + 1];
    for (int i = s; i < e; i += 32) {
        int idx = (i + lane < e) ? d_csr[i + lane] : 0;
        int cnt = min(32, e - i);
        for (int j = 0; j < cnt; j++) {
            int r = __shfl_sync(0xffffffffu, idx, j);
            float4 v = *(const float4*)(g + (size_t)r * 128 + lane * 4);
            acc.x += v.x; acc.y += v.y; acc.z += v.z; acc.w += v.w;
        }
    }
    const float dv = d_dinv[node];
    float4 b = *(const float4*)(bias + lane * 4);
    float4 o = make_float4(acc.x * dv + b.x, acc.y * dv + b.y,
                           acc.z * dv + b.z, acc.w * dv + b.w);
    *(float4*)(outh + (size_t)node * 128 + lane * 4) = o;
}

// ---------------- Aggregation 2 fused with final FC (128 -> 8) ----------------
__global__ void agg_fc_kernel(const float* __restrict__ g, const float* __restrict__ b2,
                              const float* __restrict__ Wfc, const float* __restrict__ bfc,
                              float* __restrict__ out, int n)
{
    __shared__ float sWt[CDIM * 128];
    __shared__ float sb[CDIM];
    const int tid = threadIdx.x;
    for (int i = tid; i < CDIM * 128; i += blockDim.x) {
        int f = i >> 3, j = i & 7;
        sWt[j * 128 + f] = Wfc[i];
    }
    if (tid < CDIM) sb[tid] = bfc[tid];
    __syncthreads();

    const int warp = (blockIdx.x * blockDim.x + tid) >> 5;
    const int lane = tid & 31;
    if (warp >= n) return;
    const int node = warp;

    float4 acc = *(const float4*)(g + (size_t)node * 128 + lane * 4);
    const int s = d_offs[node], e = d_offs[node + 1];
    for (int i = s; i < e; i += 32) {
        int idx = (i + lane < e) ? d_csr[i + lane] : 0;
        int cnt = min(32, e - i);
        for (int j = 0; j < cnt; j++) {
            int r = __shfl_sync(0xffffffffu, idx, j);
            float4 v = *(const float4*)(g + (size_t)r * 128 + lane * 4);
            acc.x += v.x; acc.y += v.y; acc.z += v.z; acc.w += v.w;
        }
    }
    const float dv = d_dinv[node];
    float4 bb = *(const float4*)(b2 + lane * 4);
    float h0 = acc.x * dv + bb.x;
    float h1 = acc.y * dv + bb.y;
    float h2 = acc.z * dv + bb.z;
    float h3 = acc.w * dv + bb.w;

    float p[CDIM];
    #pragma unroll
    for (int j = 0; j < CDIM; j++) {
        float4 w = *(const float4*)(sWt + j * 128 + lane * 4);
        p[j] = h0 * w.x + h1 * w.y + h2 * w.z + h3 * w.w;
    }
    #pragma unroll
    for (int o = 16; o >= 1; o >>= 1)
        #pragma unroll
        for (int j = 0; j < CDIM; j++)
            p[j] += __shfl_xor_sync(0xffffffffu, p[j], o);

    if (lane == 0) {
        float4 o0 = make_float4(p[0] + sb[0], p[1] + sb[1], p[2] + sb[2], p[3] + sb[3]);
        float4 o1 = make_float4(p[4] + sb[4], p[5] + sb[5], p[6] + sb[6], p[7] + sb[7]);
        *(float4*)(out + (size_t)node * CDIM) = o0;
        *(float4*)(out + (size_t)node * CDIM + 4) = o1;
    }
}

// ---------------- launch ----------------
extern "C" void kernel_launch(void* const* d_in, const int* in_sizes, int n_in,
                              void* d_out, int out_size)
{
    const float* x   = (const float*)d_in[0];
    const int*   ei  = (const int*)  d_in[1];
    const float* W1  = (const float*)d_in[2];
    const float* b1  = (const float*)d_in[3];
    const float* W2  = (const float*)d_in[4];
    const float* b2  = (const float*)d_in[5];
    const float* Wfc = (const float*)d_in[6];
    const float* bfc = (const float*)d_in[7];
    float* out = (float*)d_out;

    const int N = in_sizes[0] / FDIM;
    const int E = in_sizes[1] / 2;

    static const size_t GEMM_SMEM = (size_t)(64 + 128) * SA * sizeof(__nv_bfloat16); // ~147 KB
    cudaFuncSetAttribute(gemm_tc_kernel,
                         cudaFuncAttributeMaxDynamicSharedMemorySize, (int)GEMM_SMEM);

    float* bufA;  cudaGetSymbolAddress((void**)&bufA, d_bufA);
    float* bufB;  cudaGetSymbolAddress((void**)&bufB, d_bufB);

    const int nb_N = (N + 255) / 256;
    const int nb_E = (E + 255) / 256;
    const int nb_W = (N + 7) / 8;
    const int nb_G = (N + 63) / 64;

    detect_kernel<<<1, 32>>>((const unsigned int*)ei);
    zero_cnt_kernel<<<nb_N, 256>>>(N);
    hist_kernel<<<nb_E, 256>>>(ei, E);
    bsum_kernel<<<nb_N, 256>>>(N);
    bscan_kernel<<<1, 1024>>>(nb_N);
    scan_apply_kernel<<<nb_N, 256>>>(N);
    scatter_kernel<<<nb_E, 256>>>(ei, E);

    gemm_tc_kernel<<<nb_G, 256, GEMM_SMEM>>>(x, W1, bufA, N);
    agg_kernel<<<nb_W, 256>>>(bufA, b1, bufB, N);

    gemm_tc_kernel<<<nb_G, 256, GEMM_SMEM>>>(bufB, W2, bufA, N);
    agg_fc_kernel<<<nb_W, 256>>>(bufA, b2, Wfc, bfc, out, N);
}

// round 13
// speedup vs baseline: 1.1518x; 1.1518x over previous
#include <cuda_runtime.h>
#include <cuda_bf16.h>
#include <math.h>

// Problem constants (fixed-shape problem)
#define MAXN 50000
#define MAXE 800000
#define FDIM 128
#define CDIM 8
#define MAXB ((MAXN + 255) / 256)   // max scan blocks (196)

#define SA2  264    // padded bf16 row stride: 264*2B=528B, 16B-aligned, 132 words % 32 = 4 -> conflict-free
#define WSP4 (128 * SA2 * 2 / 16)   // W' tile in uint4 (4224)

// ---------------- scratch (static __device__, no allocation) ----------------
__device__ int   d_is64;
__device__ int   d_cnt[MAXN];
__device__ int   d_offs[MAXN + 1];
__device__ int   d_cursor[MAXN];
__device__ float d_dinv[MAXN];
__device__ int   d_csr[MAXE];
__device__ int   d_bsum[MAXB];
__device__ int   d_boff[MAXB];
__device__ float d_bufA[(size_t)MAXN * FDIM];
__device__ float d_bufB[(size_t)MAXN * FDIM];
__device__ uint4 d_wsplit4[WSP4];            // W' [n][264]: hi k<128 | lo k in [128,256)
__device__ uint4 d_asplit4[(size_t)MAXN * 32]; // A' [r][256] bf16: hi | lo  (32 uint4/row)

// ---------------- edge dtype detection ----------------
__global__ void detect_kernel(const unsigned int* __restrict__ w) {
    if (threadIdx.x == 0 && blockIdx.x == 0) {
        unsigned int acc = 0;
        #pragma unroll
        for (int i = 0; i < 64; i++) acc |= w[2 * i + 1];
        d_is64 = (acc == 0) ? 1 : 0;
    }
}

// ---------------- CSR construction ----------------
__global__ void zero_cnt_kernel(int n) {
    int i = blockIdx.x * blockDim.x + threadIdx.x;
    if (i < n) d_cnt[i] = 0;
}

__global__ void hist_kernel(const int* __restrict__ w, int e) {
    int i = blockIdx.x * blockDim.x + threadIdx.x;
    if (i < e) {
        int c = d_is64 ? w[2 * (e + i)] : w[e + i];
        atomicAdd(&d_cnt[c], 1);
    }
}

__global__ void bsum_kernel(int n) {
    const int b = blockIdx.x;
    const int tid = threadIdx.x;
    int i = b * 256 + tid;
    int v = (i < n) ? d_cnt[i] : 0;
    #pragma unroll
    for (int o = 16; o; o >>= 1) v += __shfl_xor_sync(0xffffffffu, v, o);
    __shared__ int ws[8];
    if ((tid & 31) == 0) ws[tid >> 5] = v;
    __syncthreads();
    if (tid == 0) {
        int s = 0;
        #pragma unroll
        for (int j = 0; j < 8; j++) s += ws[j];
        d_bsum[b] = s;
    }
}

__global__ void bscan_kernel(int nb) {
    const int tid = threadIdx.x, lane = tid & 31, wid = tid >> 5;
    int v = (tid < nb) ? d_bsum[tid] : 0;
    int x = v;
    #pragma unroll
    for (int o = 1; o < 32; o <<= 1) {
        int t = __shfl_up_sync(0xffffffffu, x, o);
        if (lane >= o) x += t;
    }
    __shared__ int ws[32];
    if (lane == 31) ws[wid] = x;
    __syncthreads();
    if (wid == 0) {
        int s = ws[lane];
        #pragma unroll
        for (int o = 1; o < 32; o <<= 1) {
            int t = __shfl_up_sync(0xffffffffu, s, o);
            if (lane >= o) s += t;
        }
        ws[lane] = s;
    }
    __syncthreads();
    int incl = x + (wid ? ws[wid - 1] : 0);
    if (tid < nb) d_boff[tid] = incl - v;
}

__global__ void scan_apply_kernel(int n) {
    const int b = blockIdx.x;
    const int tid = threadIdx.x, lane = tid & 31, wid = tid >> 5;
    int i = b * 256 + tid;
    int v = (i < n) ? d_cnt[i] : 0;
    int x = v;
    #pragma unroll
    for (int o = 1; o < 32; o <<= 1) {
        int t = __shfl_up_sync(0xffffffffu, x, o);
        if (lane >= o) x += t;
    }
    __shared__ int ws[8];
    if (lane == 31) ws[wid] = x;
    __syncthreads();
    if (wid == 0 && lane < 8) {
        int s = ws[lane];
        #pragma unroll
        for (int o = 1; o < 8; o <<= 1) {
            int t = __shfl_up_sync(0x000000ffu, s, o);
            if (lane >= o) s += t;
        }
        ws[lane] = s;
    }
    __syncthreads();
    int incl = x + (wid ? ws[wid - 1] : 0) + d_boff[b];
    if (i < n) {
        d_offs[i + 1] = incl;
        d_cursor[i]   = incl - v;
        d_dinv[i]     = rsqrtf((float)(v + 1));
        if (i == 0) d_offs[0] = 0;
    }
}

__global__ void scatter_kernel(const int* __restrict__ w, int e) {
    int i = blockIdx.x * blockDim.x + threadIdx.x;
    if (i < e) {
        int is64 = d_is64;
        int c = is64 ? w[2 * (e + i)] : w[e + i];
        int r = is64 ? w[2 * i]       : w[i];
        int p = atomicAdd(&d_cursor[c], 1);
        d_csr[p] = r;
    }
}

// ---------------- operand splitting (hoisted out of GEMM) ----------------
// W' [n][SA2] bf16: hi at k, lo at 128+k — exact smem layout, one conversion per layer.
__global__ void w_split_kernel(const float* __restrict__ W) {
    int i = blockIdx.x * blockDim.x + threadIdx.x;
    if (i < 128 * 128) {
        int k = i >> 7, nn = i & 127;
        float w = W[i];                       // W[k][n]
        __nv_bfloat16 hi = __float2bfloat16(w);
        __nv_bfloat16 lo = __float2bfloat16(w - __bfloat162float(hi));
        __nv_bfloat16* ws = (__nv_bfloat16*)d_wsplit4;
        ws[nn * SA2 + k]       = hi;
        ws[nn * SA2 + 128 + k] = lo;
    }
}

// A' [r][256] bf16: hi(128) | lo(128), packed rows (32 uint4/row).
__global__ void a_split_kernel(const float* __restrict__ A, int n) {
    int i = blockIdx.x * blockDim.x + threadIdx.x;   // over n*32 float4s
    if (i < n * 32) {
        int r = i >> 5, q = i & 31;
        float4 v = ((const float4*)A)[i];
        __nv_bfloat16 h0 = __float2bfloat16(v.x), h1 = __float2bfloat16(v.y);
        __nv_bfloat16 h2 = __float2bfloat16(v.z), h3 = __float2bfloat16(v.w);
        __nv_bfloat162 hp0 = {h0, h1}, hp1 = {h2, h3};
        __nv_bfloat162 lp0 = {__float2bfloat16(v.x - __bfloat162float(h0)),
                              __float2bfloat16(v.y - __bfloat162float(h1))};
        __nv_bfloat162 lp1 = {__float2bfloat16(v.z - __bfloat162float(h2)),
                              __float2bfloat16(v.w - __bfloat162float(h3))};
        __nv_bfloat162* as = (__nv_bfloat162*)d_asplit4;
        size_t base = (size_t)r * 128;                // row = 256 bf16 = 128 bf16x2
        as[base + q * 2]          = hp0;
        as[base + q * 2 + 1]      = hp1;
        as[base + 64 + q * 2]     = lp0;
        as[base + 64 + q * 2 + 1] = lp1;
    }
}

// ---------------- Tensor-core GEMM (split bf16, pre-split operands) ----------------
// out = dinv .* (A @ W). Tile 64x128, 8 warps (4m x 2n). 3 segments over K=128:
// (a_hi,w_hi), (a_lo,w_hi), (a_hi,w_lo). Smem ~101 KB -> 2 CTAs/SM.
#define LDSM_X4(r0, r1, r2, r3, addr) \
    asm volatile("ldmatrix.sync.aligned.m8n8.x4.shared.b16 {%0,%1,%2,%3}, [%4];" \
                 : "=r"(r0), "=r"(r1), "=r"(r2), "=r"(r3) : "r"(addr))

#define MMA16816(d, a0, a1, a2, a3, b0, b1) \
    asm volatile("mma.sync.aligned.m16n8k16.row.col.f32.bf16.bf16.f32 " \
                 "{%0,%1,%2,%3}, {%4,%5,%6,%7}, {%8,%9}, {%0,%1,%2,%3};" \
                 : "+f"(d[0]), "+f"(d[1]), "+f"(d[2]), "+f"(d[3]) \
                 : "r"(a0), "r"(a1), "r"(a2), "r"(a3), "r"(b0), "r"(b1))

__global__ void __launch_bounds__(256) gemm_tc_kernel(
    float* __restrict__ out, int n)
{
    extern __shared__ __nv_bfloat16 sh[];
    __nv_bfloat16* As = sh;              // [64][SA2]
    __nv_bfloat16* Bs = sh + 64 * SA2;   // [128][SA2]
    const int tid = threadIdx.x;
    const int row0 = blockIdx.x * 64;

    // fill B: flat vectorized copy of pre-split W'
    {
        uint4* bs4 = (uint4*)Bs;
        for (int i = tid; i < WSP4; i += 256) bs4[i] = d_wsplit4[i];
    }
    // fill A: 64 rows x 32 uint4, row-strided into padded smem
    {
        uint4* as4 = (uint4*)As;          // row r -> uint4 index r*33
        const uint4 z = make_uint4(0u, 0u, 0u, 0u);
        #pragma unroll
        for (int i = tid; i < 64 * 32; i += 256) {
            int r = i >> 5, q = i & 31;
            int gr = row0 + r;
            as4[r * 33 + q] = (gr < n) ? d_asplit4[(size_t)gr * 32 + q] : z;
        }
    }
    __syncthreads();

    const int wid = tid >> 5, l = tid & 31;
    const int wm = wid & 3, wn = wid >> 2;

    unsigned aAddr = (unsigned)__cvta_generic_to_shared(
        As + (wm * 16 + (l & 7) + ((l >> 3) & 1) * 8) * SA2 + (l >> 4) * 8);
    unsigned bAddr[4];
    #pragma unroll
    for (int t = 0; t < 4; t++)
        bAddr[t] = (unsigned)__cvta_generic_to_shared(
            Bs + (wn * 64 + t * 16 + (l & 7) + (l >> 4) * 8) * SA2 + ((l >> 3) & 1) * 8);

    float acc[8][4];
    #pragma unroll
    for (int j = 0; j < 8; j++)
        #pragma unroll
        for (int q = 0; q < 4; q++) acc[j][q] = 0.f;

    // byte offsets of the hi/lo halves within a row (128 bf16 = 256 B)
    const int segA[3] = {0, 256, 0};
    const int segB[3] = {0, 0, 256};
    #pragma unroll
    for (int s = 0; s < 3; s++) {
        #pragma unroll
        for (int k8 = 0; k8 < 8; k8++) {
            unsigned a0, a1, a2, a3;
            LDSM_X4(a0, a1, a2, a3, aAddr + segA[s] + k8 * 32);
            #pragma unroll
            for (int t = 0; t < 4; t++) {
                unsigned b0, b1, b2, b3;
                LDSM_X4(b0, b1, b2, b3, bAddr[t] + segB[s] + k8 * 32);
                MMA16816(acc[2 * t],     a0, a1, a2, a3, b0, b1);
                MMA16816(acc[2 * t + 1], a0, a1, a2, a3, b2, b3);
            }
        }
    }

    // epilogue: c frag row = l/4 (+8), col = 2(l%4)+{0,1}
    const int rl = wm * 16 + (l >> 2);
    const int cb = wn * 64 + 2 * (l & 3);
    int r0g = row0 + rl, r1g = row0 + rl + 8;
    float s0 = (r0g < n) ? d_dinv[r0g] : 0.f;
    float s1 = (r1g < n) ? d_dinv[r1g] : 0.f;
    #pragma unroll
    for (int t = 0; t < 8; t++) {
        int c = cb + t * 8;
        if (r0g < n) {
            float2 v = make_float2(acc[t][0] * s0, acc[t][1] * s0);
            *(float2*)(out + (size_t)r0g * 128 + c) = v;
        }
        if (r1g < n) {
            float2 v = make_float2(acc[t][2] * s1, acc[t][3] * s1);
            *(float2*)(out + (size_t)r1g * 128 + c) = v;
        }
    }
}

// ---------------- Aggregation: warp per node (proven R4/R6 version) ----------------
__global__ void agg_kernel(const float* __restrict__ g, const float* __restrict__ bias,
                           float* __restrict__ outh, int n)
{
    const int warp = (blockIdx.x * blockDim.x + threadIdx.x) >> 5;
    const int lane = threadIdx.x & 31;
    if (warp >= n) return;
    const int node = warp;

    float4 acc = *(const float4*)(g + (size_t)node * 128 + lane * 4);  // self loop
    const int s = d_offs[node], e = d_offs[node + 1];
    for (int i = s; i < e; i += 32) {
        int idx = (i + lane < e) ? d_csr[i + lane] : 0;
        int cnt = min(32, e - i);
        for (int j = 0; j < cnt; j++) {
            int r = __shfl_sync(0xffffffffu, idx, j);
            float4 v = *(const float4*)(g + (size_t)r * 128 + lane * 4);
            acc.x += v.x; acc.y += v.y; acc.z += v.z; acc.w += v.w;
        }
    }
    const float dv = d_dinv[node];
    float4 b = *(const float4*)(bias + lane * 4);
    float4 o = make_float4(acc.x * dv + b.x, acc.y * dv + b.y,
                           acc.z * dv + b.z, acc.w * dv + b.w);
    *(float4*)(outh + (size_t)node * 128 + lane * 4) = o;
}

// ---------------- Aggregation 2 fused with final FC (128 -> 8) ----------------
__global__ void agg_fc_kernel(const float* __restrict__ g, const float* __restrict__ b2,
                              const float* __restrict__ Wfc, const float* __restrict__ bfc,
                              float* __restrict__ out, int n)
{
    __shared__ float sWt[CDIM * 128];
    __shared__ float sb[CDIM];
    const int tid = threadIdx.x;
    for (int i = tid; i < CDIM * 128; i += blockDim.x) {
        int f = i >> 3, j = i & 7;
        sWt[j * 128 + f] = Wfc[i];
    }
    if (tid < CDIM) sb[tid] = bfc[tid];
    __syncthreads();

    const int warp = (blockIdx.x * blockDim.x + tid) >> 5;
    const int lane = tid & 31;
    if (warp >= n) return;
    const int node = warp;

    float4 acc = *(const float4*)(g + (size_t)node * 128 + lane * 4);
    const int s = d_offs[node], e = d_offs[node + 1];
    for (int i = s; i < e; i += 32) {
        int idx = (i + lane < e) ? d_csr[i + lane] : 0;
        int cnt = min(32, e - i);
        for (int j = 0; j < cnt; j++) {
            int r = __shfl_sync(0xffffffffu, idx, j);
            float4 v = *(const float4*)(g + (size_t)r * 128 + lane * 4);
            acc.x += v.x; acc.y += v.y; acc.z += v.z; acc.w += v.w;
        }
    }
    const float dv = d_dinv[node];
    float4 bb = *(const float4*)(b2 + lane * 4);
    float h0 = acc.x * dv + bb.x;
    float h1 = acc.y * dv + bb.y;
    float h2 = acc.z * dv + bb.z;
    float h3 = acc.w * dv + bb.w;

    float p[CDIM];
    #pragma unroll
    for (int j = 0; j < CDIM; j++) {
        float4 w = *(const float4*)(sWt + j * 128 + lane * 4);
        p[j] = h0 * w.x + h1 * w.y + h2 * w.z + h3 * w.w;
    }
    #pragma unroll
    for (int o = 16; o >= 1; o >>= 1)
        #pragma unroll
        for (int j = 0; j < CDIM; j++)
            p[j] += __shfl_xor_sync(0xffffffffu, p[j], o);

    if (lane == 0) {
        float4 o0 = make_float4(p[0] + sb[0], p[1] + sb[1], p[2] + sb[2], p[3] + sb[3]);
        float4 o1 = make_float4(p[4] + sb[4], p[5] + sb[5], p[6] + sb[6], p[7] + sb[7]);
        *(float4*)(out + (size_t)node * CDIM) = o0;
        *(float4*)(out + (size_t)node * CDIM + 4) = o1;
    }
}

// ---------------- launch ----------------
extern "C" void kernel_launch(void* const* d_in, const int* in_sizes, int n_in,
                              void* d_out, int out_size)
{
    const float* x   = (const float*)d_in[0];
    const int*   ei  = (const int*)  d_in[1];
    const float* W1  = (const float*)d_in[2];
    const float* b1  = (const float*)d_in[3];
    const float* W2  = (const float*)d_in[4];
    const float* b2  = (const float*)d_in[5];
    const float* Wfc = (const float*)d_in[6];
    const float* bfc = (const float*)d_in[7];
    float* out = (float*)d_out;

    const int N = in_sizes[0] / FDIM;
    const int E = in_sizes[1] / 2;

    static const size_t GEMM_SMEM = (size_t)(64 + 128) * SA2 * sizeof(__nv_bfloat16); // ~101 KB
    cudaFuncSetAttribute(gemm_tc_kernel,
                         cudaFuncAttributeMaxDynamicSharedMemorySize, (int)GEMM_SMEM);

    float* bufA;  cudaGetSymbolAddress((void**)&bufA, d_bufA);
    float* bufB;  cudaGetSymbolAddress((void**)&bufB, d_bufB);

    const int nb_N = (N + 255) / 256;
    const int nb_E = (E + 255) / 256;
    const int nb_W = (N + 7) / 8;
    const int nb_G = (N + 63) / 64;
    const int nb_S = (N * 32 + 255) / 256;

    detect_kernel<<<1, 32>>>((const unsigned int*)ei);
    zero_cnt_kernel<<<nb_N, 256>>>(N);
    hist_kernel<<<nb_E, 256>>>(ei, E);
    bsum_kernel<<<nb_N, 256>>>(N);
    bscan_kernel<<<1, 1024>>>(nb_N);
    scan_apply_kernel<<<nb_N, 256>>>(N);
    scatter_kernel<<<nb_E, 256>>>(ei, E);

    // layer 1
    w_split_kernel<<<64, 256>>>(W1);
    a_split_kernel<<<nb_S, 256>>>(x, N);
    gemm_tc_kernel<<<nb_G, 256, GEMM_SMEM>>>(bufA, N);
    agg_kernel<<<nb_W, 256>>>(bufA, b1, bufB, N);

    // layer 2
    w_split_kernel<<<64, 256>>>(W2);
    a_split_kernel<<<nb_S, 256>>>(bufB, N);
    gemm_tc_kernel<<<nb_G, 256, GEMM_SMEM>>>(bufA, N);
    agg_fc_kernel<<<nb_W, 256>>>(bufA, b2, Wfc, bfc, out, N);
}